// round 10
// baseline (speedup 1.0000x reference)
#include <cuda_runtime.h>
#include <cstdint>

#define IMG_N  2048
#define OW     2044
#define OH     2044
#define TW     128
#define TH     8
#define IR     12          // TH + 4 input rows
#define IC     132         // TW + 4 input cols
#define ICP    136         // padded col stride (bf16) for staged planes
#define NTH    256

// smem layout (bytes)
#define SX_OFF     0
#define SX_BYTES   (IR * IC * 4)               // 6336: raw int tile
#define PL_OFF     SX_BYTES                    // bf16 planes [IR][7][ICP]
#define PL_BYTES   (IR * 7 * ICP * 2)          // 22848
#define W_OFF      (PL_OFF + PL_BYTES)         // 29184 (16B aligned)
#define SMEM_BYTES (W_OFF + 15 * 8 * 8)        // + padded weight pairs (~30144)

typedef unsigned long long ull;
typedef unsigned int u32;

__device__ __forceinline__ void fma2(ull& acc, ull a, ull b) {
    asm("fma.rn.f32x2 %0, %1, %2, %0;" : "+l"(acc) : "l"(a), "l"(b));
}
__device__ __forceinline__ ull pack2(u32 lo, u32 hi) {
    ull r; asm("mov.b64 %0, {%1, %2};" : "=l"(r) : "r"(lo), "r"(hi)); return r;
}
__device__ __forceinline__ ull mkpair_lohi(u32 u) {
    ull r;
    asm("{.reg .b32 a, b;\n\t"
        "shl.b32 a, %1, 16;\n\t"
        "and.b32 b, %1, 0xFFFF0000;\n\t"
        "mov.b64 %0, {a, b};}" : "=l"(r) : "r"(u));
    return r;
}
__device__ __forceinline__ ull mkpair_cross(u32 u, u32 v) {
    ull r;
    asm("{.reg .b32 a, b;\n\t"
        "and.b32 a, %1, 0xFFFF0000;\n\t"
        "shl.b32 b, %2, 16;\n\t"
        "mov.b64 %0, {a, b};}" : "=l"(r) : "r"(u), "r"(v));
    return r;
}

// Expand np bit-planes [z0, z0+np) of the int tile into bf16 planes (exact).
__device__ __forceinline__ void expand_planes(const int* __restrict__ sx,
                                              uint16_t* __restrict__ pl,
                                              int tid, int z0, int np)
{
    for (int idx = tid; idx < IR * (IC / 2); idx += NTH) {
        int rr = idx / (IC / 2);
        int c2 = (idx - rr * (IC / 2)) * 2;
        const int* src = sx + rr * IC + c2;
        u32 v0 = (u32)src[0] >> z0;
        u32 v1 = (u32)src[1] >> z0;
        u32* dst = reinterpret_cast<u32*>(pl + (rr * 7) * ICP + c2);
        #pragma unroll 7
        for (int p = 0; p < np; p++) {
            u32 val = ((v0 >> p) & 1u) * 0x3F80u
                    | ((v1 >> p) & 1u) * 0x3F800000u;
            dst[p * (ICP / 2)] = val;
        }
    }
}

// One z-pass: NZ outputs, staged planes p in [0, NZ+2), 4 cols/thread (w-paired).
// Weights via per-(kk,d) warp-uniform broadcast LDS (no reg cost).
template<int NZ>
__device__ __forceinline__ void run_pass(const uint16_t* __restrict__ pl,
                                         const ull* __restrict__ wps,
                                         int r, int col0, ull* accA, ull* accB)
{
    #pragma unroll
    for (int z = 0; z < NZ; z++) { accA[z] = 0ull; accB[z] = 0ull; }

    #pragma unroll 1
    for (int i = 0; i < 5; i++) {
        const uint16_t* rowi = pl + ((r + i) * 7) * ICP + col0;
        const ull* wrow = wps + i * 8;        // row (d*5+i)*8; d term added below

        #pragma unroll
        for (int kk = 0; kk < NZ + 2; kk++) {
            const u32* rk = reinterpret_cast<const u32*>(rowi + kk * ICP);
            uint2 ma = *reinterpret_cast<const uint2*>(rk);       // bf16 cols 0..3
            uint2 mb = *reinterpret_cast<const uint2*>(rk + 2);   // bf16 cols 4..7

            ull S[7];
            S[0] = mkpair_lohi (ma.x);
            S[1] = mkpair_cross(ma.x, ma.y);
            S[2] = mkpair_lohi (ma.y);
            S[3] = mkpair_cross(ma.y, mb.x);
            S[4] = mkpair_lohi (mb.x);
            S[5] = mkpair_cross(mb.x, mb.y);
            S[6] = mkpair_lohi (mb.y);

            #pragma unroll
            for (int d = 0; d < 3; d++) {
                const int zz = kk - d;            // compile-time per (kk,d)
                if (zz >= 0 && zz < NZ) {
                    const ull* wd = wrow + d * 40;   // (d*5+i)*8
                    ulonglong2 w01 = *reinterpret_cast<const ulonglong2*>(wd);
                    ulonglong2 w23 = *reinterpret_cast<const ulonglong2*>(wd + 2);
                    ull        w4  = wd[4];
                    fma2(accA[zz], w01.x, S[0]);  fma2(accB[zz], w01.x, S[2]);
                    fma2(accA[zz], w01.y, S[1]);  fma2(accB[zz], w01.y, S[3]);
                    fma2(accA[zz], w23.x, S[2]);  fma2(accB[zz], w23.x, S[4]);
                    fma2(accA[zz], w23.y, S[3]);  fma2(accB[zz], w23.y, S[5]);
                    fma2(accA[zz], w4,    S[4]);  fma2(accB[zz], w4,    S[6]);
                }
            }
        }
    }
}

template<int NZ>
__device__ __forceinline__ void store_pass(float* __restrict__ out, int h, int w,
                                           int z0, float bv,
                                           const ull* accA, const ull* accB)
{
    if (h >= OH || w >= OW) return;
    const bool full = (w + 4 <= OW);
    #pragma unroll
    for (int zz = 0; zz < NZ; zz++) {
        float2 a = *reinterpret_cast<const float2*>(&accA[zz]);
        float2 b = *reinterpret_cast<const float2*>(&accB[zz]);
        size_t off = ((size_t)(z0 + zz) * OH + h) * OW + w;
        if (full) {
            *reinterpret_cast<float4*>(out + off) =
                make_float4(a.x + bv, a.y + bv, b.x + bv, b.y + bv);
        } else {
            float vals[4] = { a.x + bv, a.y + bv, b.x + bv, b.y + bv };
            #pragma unroll
            for (int c = 0; c < 4; c++)
                if (w + c < OW) out[off + c] = vals[c];
        }
    }
}

__global__ void __launch_bounds__(NTH, 5)
conv2dto3d_kernel(const int* __restrict__ x,
                  const float* __restrict__ weight,
                  const float* __restrict__ bias,
                  float* __restrict__ out)
{
    extern __shared__ unsigned char smem[];
    int*       sx  = reinterpret_cast<int*>(smem + SX_OFF);
    uint16_t*  pl  = reinterpret_cast<uint16_t*>(smem + PL_OFF);
    ull*       wps = reinterpret_cast<ull*>(smem + W_OFF);

    const int tid   = threadIdx.x;
    const int wbase = blockIdx.x * TW;
    const int hbase = blockIdx.y * TH;

    if (tid < 75) {
        int d = tid / 25, rem = tid - d * 25;
        int i = rem / 5,  j = rem - i * 5;
        u32 wb = __float_as_uint(weight[tid]);
        wps[(d * 5 + i) * 8 + j] = pack2(wb, wb);
    }

    // ---- load int tile (clamped) ----
    for (int idx = tid; idx < IR * IC; idx += NTH) {
        int rr = idx / IC, cc = idx - rr * IC;
        int ri = hbase + rr; if (ri > IMG_N - 1) ri = IMG_N - 1;
        int ci = wbase + cc; if (ci > IMG_N - 1) ci = IMG_N - 1;
        sx[idx] = x[ri * IMG_N + ci];
    }
    __syncthreads();

    const int g = tid & 31;          // 32 column groups of 4
    const int r = tid >> 5;          // local row 0..7
    const int col0 = g * 4;
    const int h = hbase + r;
    const int w = wbase + col0;
    const float bv = bias[0];

    ull accA[5], accB[5];

    // ---- pass 0: z in [0..4], planes 0..6 ----
    expand_planes(sx, pl, tid, 0, 7);
    __syncthreads();
    run_pass<5>(pl, wps, r, col0, accA, accB);
    __syncthreads();
    store_pass<5>(out, h, w, 0, bv, accA, accB);

    // ---- pass 1: z in [5..9], planes 5..11 ----
    expand_planes(sx, pl, tid, 5, 7);
    __syncthreads();
    run_pass<5>(pl, wps, r, col0, accA, accB);
    __syncthreads();
    store_pass<5>(out, h, w, 5, bv, accA, accB);

    // ---- pass 2: z in [10..13], planes 10..15 ----
    expand_planes(sx, pl, tid, 10, 6);
    __syncthreads();
    run_pass<4>(pl, wps, r, col0, accA, accB);
    store_pass<4>(out, h, w, 10, bv, accA, accB);
}

extern "C" void kernel_launch(void* const* d_in, const int* in_sizes, int n_in,
                              void* d_out, int out_size)
{
    const int*   x      = (const int*)d_in[0];
    const float* weight = (const float*)d_in[1];
    const float* bias   = (const float*)d_in[2];
    float*       out    = (float*)d_out;

    cudaFuncSetAttribute(conv2dto3d_kernel,
                         cudaFuncAttributeMaxDynamicSharedMemorySize, SMEM_BYTES);

    dim3 grid((OW + TW - 1) / TW, (OH + TH - 1) / TH);   // 16 x 256
    conv2dto3d_kernel<<<grid, NTH, SMEM_BYTES>>>(x, weight, bias, out);
}

// round 11
// speedup vs baseline: 1.2034x; 1.2034x over previous
#include <cuda_runtime.h>
#include <cstdint>

#define IMG_N  2048
#define OW     2044
#define OH     2044
#define TW     128
#define TH     16          // output rows per CTA (2 per thread)
#define IR     20          // TH + 4 input rows
#define IC     132         // TW + 4 input cols
#define ICP    136         // padded col stride (bf16) for staged planes
#define NTH    256

// smem layout (bytes)
#define SX_OFF     0
#define SX_BYTES   (IR * IC * 4)               // 10560: raw int tile
#define PL_OFF     SX_BYTES                    // bf16 planes [IR][7][ICP]
#define PL_BYTES   (IR * 7 * ICP * 2)          // 38080
#define W_OFF      (PL_OFF + PL_BYTES)         // 48640 (16B aligned)
#define SMEM_BYTES (W_OFF + 15 * 8 * 8)        // ~49.6 KB

typedef unsigned long long ull;
typedef unsigned int u32;

__device__ __forceinline__ void fma2(ull& acc, ull a, ull b) {
    asm("fma.rn.f32x2 %0, %1, %2, %0;" : "+l"(acc) : "l"(a), "l"(b));
}
__device__ __forceinline__ ull pack2(u32 lo, u32 hi) {
    ull r; asm("mov.b64 %0, {%1, %2};" : "=l"(r) : "r"(lo), "r"(hi)); return r;
}
__device__ __forceinline__ ull mkpair_lohi(u32 u) {
    ull r;
    asm("{.reg .b32 a, b;\n\t"
        "shl.b32 a, %1, 16;\n\t"
        "and.b32 b, %1, 0xFFFF0000;\n\t"
        "mov.b64 %0, {a, b};}" : "=l"(r) : "r"(u));
    return r;
}
__device__ __forceinline__ ull mkpair_cross(u32 u, u32 v) {
    ull r;
    asm("{.reg .b32 a, b;\n\t"
        "and.b32 a, %1, 0xFFFF0000;\n\t"
        "shl.b32 b, %2, 16;\n\t"
        "mov.b64 %0, {a, b};}" : "=l"(r) : "r"(u), "r"(v));
    return r;
}

// Expand np bit-planes [z0, z0+np) of the int tile into bf16 planes (exact).
__device__ __forceinline__ void expand_planes(const int* __restrict__ sx,
                                              uint16_t* __restrict__ pl,
                                              int tid, int z0, int np)
{
    for (int idx = tid; idx < IR * (IC / 2); idx += NTH) {
        int rr = idx / (IC / 2);
        int c2 = (idx - rr * (IC / 2)) * 2;
        const int* src = sx + rr * IC + c2;
        u32 v0 = (u32)src[0] >> z0;
        u32 v1 = (u32)src[1] >> z0;
        u32* dst = reinterpret_cast<u32*>(pl + (rr * 7) * ICP + c2);
        #pragma unroll 7
        for (int p = 0; p < np; p++) {
            u32 val = ((v0 >> p) & 1u) * 0x3F80u
                    | ((v1 >> p) & 1u) * 0x3F800000u;
            dst[p * (ICP / 2)] = val;
        }
    }
}

// 10 FMA2s for one (d) tap-row into one output-row's accumulators.
__device__ __forceinline__ void tap_row(ull& aA, ull& aB, const ull* wd, const ull* S)
{
    ulonglong2 w01 = *reinterpret_cast<const ulonglong2*>(wd);
    ulonglong2 w23 = *reinterpret_cast<const ulonglong2*>(wd + 2);
    ull        w4  = wd[4];
    fma2(aA, w01.x, S[0]);  fma2(aB, w01.x, S[2]);
    fma2(aA, w01.y, S[1]);  fma2(aB, w01.y, S[3]);
    fma2(aA, w23.x, S[2]);  fma2(aB, w23.x, S[4]);
    fma2(aA, w23.y, S[3]);  fma2(aB, w23.y, S[5]);
    fma2(aA, w4,    S[4]);  fma2(aB, w4,    S[6]);
}

// One z-pass: NZ outputs for TWO adjacent output rows (2*rp, 2*rp+1).
// S pairs are loaded once per (input row, kk) and shared by both rows.
template<int NZ>
__device__ __forceinline__ void run_pass(const uint16_t* __restrict__ pl,
                                         const ull* __restrict__ wps,
                                         int rp, int col0,
                                         ull a0A[], ull a0B[], ull a1A[], ull a1B[])
{
    #pragma unroll
    for (int z = 0; z < NZ; z++) {
        a0A[z] = 0ull; a0B[z] = 0ull; a1A[z] = 0ull; a1B[z] = 0ull;
    }

    #pragma unroll 1
    for (int ri = 0; ri < 6; ri++) {            // input row = 2*rp + ri
        const uint16_t* rowp = pl + ((2 * rp + ri) * 7) * ICP + col0;
        const int i0 = ri;                       // tap row for output row 0
        const int i1 = ri - 1;                   // tap row for output row 1
        const bool use0 = (ri <= 4);
        const bool use1 = (ri >= 1);

        #pragma unroll
        for (int kk = 0; kk < NZ + 2; kk++) {
            const u32* rk = reinterpret_cast<const u32*>(rowp + kk * ICP);
            uint2 ma = *reinterpret_cast<const uint2*>(rk);       // bf16 cols 0..3
            uint2 mb = *reinterpret_cast<const uint2*>(rk + 2);   // bf16 cols 4..7

            ull S[7];
            S[0] = mkpair_lohi (ma.x);
            S[1] = mkpair_cross(ma.x, ma.y);
            S[2] = mkpair_lohi (ma.y);
            S[3] = mkpair_cross(ma.y, mb.x);
            S[4] = mkpair_lohi (mb.x);
            S[5] = mkpair_cross(mb.x, mb.y);
            S[6] = mkpair_lohi (mb.y);

            #pragma unroll
            for (int d = 0; d < 3; d++) {
                const int zz = kk - d;                   // compile-time
                if (zz >= 0 && zz < NZ) {
                    if (use0)
                        tap_row(a0A[zz], a0B[zz], wps + (d * 5 + i0) * 8, S);
                    if (use1)
                        tap_row(a1A[zz], a1B[zz], wps + (d * 5 + i1) * 8, S);
                }
            }
        }
    }
}

__device__ __forceinline__ void store_row(float* __restrict__ out, int h, int w,
                                          int z0, int nz, float bv,
                                          const ull* accA, const ull* accB)
{
    if (h >= OH || w >= OW) return;
    const bool full = (w + 4 <= OW);
    for (int zz = 0; zz < nz; zz++) {
        float2 a = *reinterpret_cast<const float2*>(&accA[zz]);
        float2 b = *reinterpret_cast<const float2*>(&accB[zz]);
        size_t off = ((size_t)(z0 + zz) * OH + h) * OW + w;
        if (full) {
            *reinterpret_cast<float4*>(out + off) =
                make_float4(a.x + bv, a.y + bv, b.x + bv, b.y + bv);
        } else {
            float vals[4] = { a.x + bv, a.y + bv, b.x + bv, b.y + bv };
            #pragma unroll
            for (int c = 0; c < 4; c++)
                if (w + c < OW) out[off + c] = vals[c];
        }
    }
}

__global__ void __launch_bounds__(NTH, 3)
conv2dto3d_kernel(const int* __restrict__ x,
                  const float* __restrict__ weight,
                  const float* __restrict__ bias,
                  float* __restrict__ out)
{
    extern __shared__ unsigned char smem[];
    int*       sx  = reinterpret_cast<int*>(smem + SX_OFF);
    uint16_t*  pl  = reinterpret_cast<uint16_t*>(smem + PL_OFF);
    ull*       wps = reinterpret_cast<ull*>(smem + W_OFF);

    const int tid   = threadIdx.x;
    const int wbase = blockIdx.x * TW;
    const int hbase = blockIdx.y * TH;

    if (tid < 75) {
        int d = tid / 25, rem = tid - d * 25;
        int i = rem / 5,  j = rem - i * 5;
        u32 wb = __float_as_uint(weight[tid]);
        wps[(d * 5 + i) * 8 + j] = pack2(wb, wb);
    }

    // ---- load int tile (clamped) ----
    for (int idx = tid; idx < IR * IC; idx += NTH) {
        int rr = idx / IC, cc = idx - rr * IC;
        int ri = hbase + rr; if (ri > IMG_N - 1) ri = IMG_N - 1;
        int ci = wbase + cc; if (ci > IMG_N - 1) ci = IMG_N - 1;
        sx[idx] = x[ri * IMG_N + ci];
    }
    __syncthreads();

    const int g  = tid & 31;         // 32 column groups of 4
    const int rp = tid >> 5;         // row pair 0..7 -> output rows 2rp, 2rp+1
    const int col0 = g * 4;
    const int h0 = hbase + 2 * rp;
    const int w  = wbase + col0;
    const float bv = bias[0];

    ull a0A[5], a0B[5], a1A[5], a1B[5];

    // ---- pass 0: z in [0..4], planes 0..6 ----
    expand_planes(sx, pl, tid, 0, 7);
    __syncthreads();
    run_pass<5>(pl, wps, rp, col0, a0A, a0B, a1A, a1B);
    __syncthreads();
    store_row(out, h0,     w, 0, 5, bv, a0A, a0B);
    store_row(out, h0 + 1, w, 0, 5, bv, a1A, a1B);

    // ---- pass 1: z in [5..9], planes 5..11 ----
    expand_planes(sx, pl, tid, 5, 7);
    __syncthreads();
    run_pass<5>(pl, wps, rp, col0, a0A, a0B, a1A, a1B);
    __syncthreads();
    store_row(out, h0,     w, 5, 5, bv, a0A, a0B);
    store_row(out, h0 + 1, w, 5, 5, bv, a1A, a1B);

    // ---- pass 2: z in [10..13], planes 10..15 ----
    expand_planes(sx, pl, tid, 10, 6);
    __syncthreads();
    run_pass<4>(pl, wps, rp, col0, a0A, a0B, a1A, a1B);
    store_row(out, h0,     w, 10, 4, bv, a0A, a0B);
    store_row(out, h0 + 1, w, 10, 4, bv, a1A, a1B);
}

extern "C" void kernel_launch(void* const* d_in, const int* in_sizes, int n_in,
                              void* d_out, int out_size)
{
    const int*   x      = (const int*)d_in[0];
    const float* weight = (const float*)d_in[1];
    const float* bias   = (const float*)d_in[2];
    float*       out    = (float*)d_out;

    cudaFuncSetAttribute(conv2dto3d_kernel,
                         cudaFuncAttributeMaxDynamicSharedMemorySize, SMEM_BYTES);

    dim3 grid((OW + TW - 1) / TW, (OH + TH - 1) / TH);   // 16 x 128
    conv2dto3d_kernel<<<grid, NTH, SMEM_BYTES>>>(x, weight, bias, out);
}

// round 12
// speedup vs baseline: 1.7771x; 1.4768x over previous
#include <cuda_runtime.h>
#include <cstdint>

#define IMG_N  2048
#define OW     2044
#define OH     2044
#define TW     128
#define TH     8
#define IR     12          // TH + 4 input rows
#define IC     132         // TW + 4 input cols
#define ICP    136         // padded col stride (bf16 elements)
#define NTH    256

#define PLANES_U16 (IR * 16 * ICP)           // 26112 bf16
#define SMEM_BYTES (PLANES_U16 * 2)          // 52224 bytes (planes only)

typedef unsigned long long ull;
typedef unsigned int u32;

__constant__ float c_w[75];                   // weight[d][i][j], d*25+i*5+j

__device__ __forceinline__ void fma2(ull& acc, ull a, ull b) {
    asm("fma.rn.f32x2 %0, %1, %2, %0;" : "+l"(acc) : "l"(a), "l"(b));
}
// duplicate one float into a f32x2 pair (uniform source -> UR-promotable)
__device__ __forceinline__ ull dup2(float w) {
    ull r; asm("mov.b64 %0, {%1, %1};" : "=l"(r) : "f"(w)); return r;
}
__device__ __forceinline__ ull mkpair_lohi(u32 u) {
    ull r;
    asm("{.reg .b32 a, b;\n\t"
        "shl.b32 a, %1, 16;\n\t"
        "and.b32 b, %1, 0xFFFF0000;\n\t"
        "mov.b64 %0, {a, b};}" : "=l"(r) : "r"(u));
    return r;
}
__device__ __forceinline__ ull mkpair_cross(u32 u, u32 v) {
    ull r;
    asm("{.reg .b32 a, b;\n\t"
        "and.b32 a, %1, 0xFFFF0000;\n\t"
        "shl.b32 b, %2, 16;\n\t"
        "mov.b64 %0, {a, b};}" : "=l"(r) : "r"(u), "r"(v));
    return r;
}

// One z-pass: outputs z in [ZLO, ZLO+6], consuming bit planes k in [ZLO, ZLO+8].
template<int ZLO>
__device__ __forceinline__ void run_pass(const uint16_t* __restrict__ sp,
                                         int r, int col0, ull* accA, ull* accB)
{
    #pragma unroll
    for (int z = 0; z < 7; z++) { accA[z] = 0ull; accB[z] = 0ull; }

    #pragma unroll 1
    for (int i = 0; i < 5; i++) {
        // 15 weight pairs for this i, from constant memory (uniform path)
        ull wv[15];
        #pragma unroll
        for (int d = 0; d < 3; d++)
            #pragma unroll
            for (int j = 0; j < 5; j++)
                wv[d * 5 + j] = dup2(c_w[d * 25 + i * 5 + j]);

        const uint16_t* rowi = sp + ((r + i) * 16 + ZLO) * ICP + col0;

        #pragma unroll
        for (int kk = 0; kk < 9; kk++) {
            const u32* rk = reinterpret_cast<const u32*>(rowi + kk * ICP);
            uint2 ma = *reinterpret_cast<const uint2*>(rk);       // bf16 cols 0..3
            uint2 mb = *reinterpret_cast<const uint2*>(rk + 2);   // bf16 cols 4..7

            ull S[7];
            S[0] = mkpair_lohi (ma.x);
            S[1] = mkpair_cross(ma.x, ma.y);
            S[2] = mkpair_lohi (ma.y);
            S[3] = mkpair_cross(ma.y, mb.x);
            S[4] = mkpair_lohi (mb.x);
            S[5] = mkpair_cross(mb.x, mb.y);
            S[6] = mkpair_lohi (mb.y);

            #pragma unroll
            for (int d = 0; d < 3; d++) {
                const int zz = kk - d;                 // compile-time per (kk,d)
                if (zz >= 0 && zz < 7) {
                    #pragma unroll
                    for (int j = 0; j < 5; j++) {
                        const ull w = wv[d * 5 + j];
                        fma2(accA[zz], w, S[j]);       // cols (c, c+1)
                        fma2(accB[zz], w, S[j + 2]);   // cols (c+2, c+3)
                    }
                }
            }
        }
    }
}

template<int ZLO>
__device__ __forceinline__ void store_pass(float* __restrict__ out, int h, int w,
                                           float bv, const ull* accA, const ull* accB)
{
    if (h >= OH || w >= OW) return;
    const bool full = (w + 4 <= OW);
    #pragma unroll
    for (int zz = 0; zz < 7; zz++) {
        float2 a = *reinterpret_cast<const float2*>(&accA[zz]);
        float2 b = *reinterpret_cast<const float2*>(&accB[zz]);
        size_t off = ((size_t)(ZLO + zz) * OH + h) * OW + w;
        if (full) {
            *reinterpret_cast<float4*>(out + off) =
                make_float4(a.x + bv, a.y + bv, b.x + bv, b.y + bv);
        } else {
            float vals[4] = { a.x + bv, a.y + bv, b.x + bv, b.y + bv };
            #pragma unroll
            for (int c = 0; c < 4; c++)
                if (w + c < OW) out[off + c] = vals[c];
        }
    }
}

__global__ void __launch_bounds__(NTH, 3)
conv2dto3d_kernel(const int* __restrict__ x,
                  const float* __restrict__ bias,
                  float* __restrict__ out)
{
    extern __shared__ unsigned char smem[];
    uint16_t* sp = reinterpret_cast<uint16_t*>(smem);

    const int tid   = threadIdx.x;
    const int wbase = blockIdx.x * TW;
    const int hbase = blockIdx.y * TH;

    // ---- expand tile to bf16 bit planes (exact): sp[rr][k][cc] ----
    for (int pp = tid; pp < IR * (IC / 2); pp += NTH) {
        int rr = pp / (IC / 2);
        int c2 = (pp - rr * (IC / 2)) * 2;
        int ri = hbase + rr;     if (ri > IMG_N - 1) ri = IMG_N - 1;
        int c0 = wbase + c2;     if (c0 > IMG_N - 1) c0 = IMG_N - 1;
        int c1 = wbase + c2 + 1; if (c1 > IMG_N - 1) c1 = IMG_N - 1;
        u32 a0 = (u32)x[ri * IMG_N + c0];
        u32 a1 = (u32)x[ri * IMG_N + c1];
        #pragma unroll
        for (int k = 0; k < 16; k++) {
            u32 val = ((a0 >> k) & 1u) * 0x3F80u
                    | ((a1 >> k) & 1u) * 0x3F800000u;
            *reinterpret_cast<u32*>(sp + (rr * 16 + k) * ICP + c2) = val;
        }
    }
    __syncthreads();

    const int g = tid & 31;
    const int r = tid >> 5;
    const int col0 = g * 4;
    const int h = hbase + r;
    const int w = wbase + col0;
    const float bv = bias[0];

    ull accA[7], accB[7];

    run_pass<0>(sp, r, col0, accA, accB);
    store_pass<0>(out, h, w, bv, accA, accB);

    run_pass<7>(sp, r, col0, accA, accB);
    store_pass<7>(out, h, w, bv, accA, accB);
}

extern "C" void kernel_launch(void* const* d_in, const int* in_sizes, int n_in,
                              void* d_out, int out_size)
{
    const int*   x      = (const int*)d_in[0];
    const float* weight = (const float*)d_in[1];
    const float* bias   = (const float*)d_in[2];
    float*       out    = (float*)d_out;

    // weights -> constant bank (async D2D, graph-capturable, same-stream ordered)
    cudaMemcpyToSymbolAsync(c_w, weight, 75 * sizeof(float), 0,
                            cudaMemcpyDeviceToDevice, 0);

    cudaFuncSetAttribute(conv2dto3d_kernel,
                         cudaFuncAttributeMaxDynamicSharedMemorySize, SMEM_BYTES);

    dim3 grid((OW + TW - 1) / TW, (OH + TH - 1) / TH);   // 16 x 256
    conv2dto3d_kernel<<<grid, NTH, SMEM_BYTES>>>(x, bias, out);
}